// round 9
// baseline (speedup 1.0000x reference)
#include <cuda_runtime.h>

#define Wd 512
#define Hd 512
#define W2 (Wd / 2)
#define NT 256
#define RSTRIP 64
#define LDW 520            // padded row: [0,1] left guard, data [2..513], [514..] right guard
#define THIRD 0.3333333333333333f
#define EPS 0.01f

typedef unsigned long long ull;

static __device__ __forceinline__ ull U(float2 v) { ull r; memcpy(&r, &v, 8); return r; }
static __device__ __forceinline__ float2 F(ull u) { float2 v; memcpy(&v, &u, 8); return v; }

static __device__ __forceinline__ float2 f2add(float2 a, float2 b) {
    ull r; asm("add.rn.f32x2 %0,%1,%2;" : "=l"(r) : "l"(U(a)), "l"(U(b))); return F(r);
}
static __device__ __forceinline__ float2 f2mul(float2 a, float2 b) {
    ull r; asm("mul.rn.f32x2 %0,%1,%2;" : "=l"(r) : "l"(U(a)), "l"(U(b))); return F(r);
}
static __device__ __forceinline__ float2 f2fma(float2 a, float2 b, float2 c) {
    ull r; asm("fma.rn.f32x2 %0,%1,%2,%3;" : "=l"(r) : "l"(U(a)), "l"(U(b)), "l"(U(c))); return F(r);
}
static __device__ __forceinline__ float2 mk2(float a, float b) { float2 v; v.x = a; v.y = b; return v; }

__global__ __launch_bounds__(NT, 4)
void gf_kernel(const float* __restrict__ gI, const float* __restrict__ gP,
               float* __restrict__ gO)
{
    __shared__ __align__(16) float smI[2][LDW], smP[2][LDW], smA[2][LDW], smB[2][LDW];

    const int t  = threadIdx.x;
    const int x0 = 2 * t;                 // padded data index of own pair = x0+2
    const int y0 = blockIdx.x * RSTRIP;
    const size_t base = (size_t)blockIdx.y * (size_t)(Wd * Hd);
    const float2* __restrict__ GI = (const float2*)(gI + base);
    const float2* __restrict__ GP = (const float2*)(gP + base);
    float2* __restrict__ GO = (float2*)(gO + base);

    const float icx0 = (t == 0)      ? 0.5f : THIRD;   // count_include_pad=False col counts
    const float icx1 = (t == NT - 1) ? 0.5f : THIRD;

    // permanent zero guards (stores each iter touch only [2..513])
    if (t < 2) {
        const int g = (t == 0) ? 1 : 514;
        #pragma unroll
        for (int b = 0; b < 2; ++b) {
            smI[b][g] = 0.f; smP[b][g] = 0.f; smA[b][g] = 0.f; smB[b][g] = 0.f;
        }
    }

    const float2 z2 = mk2(0.f, 0.f);

    // vertical sliding state (pair-sum ps + last h-row l), all packed float2
    float2 psI = z2, lI = z2, psP = z2, lP = z2;
    float2 psII = z2, lII = z2, psIP = z2, lIP = z2;
    float2 psA = z2, lA = z2, psB = z2, lB = z2;
    float2 avP = z2, bvP = z2;

    // prologue rows y0-2 (cur) and y0-1 (next)
    float2 viC = z2, vpC = z2, viN = z2, vpN = z2;
    if (y0 >= 2) {
        viC = GI[(y0 - 2) * W2 + t]; vpC = GP[(y0 - 2) * W2 + t];
        viN = GI[(y0 - 1) * W2 + t]; vpN = GP[(y0 - 1) * W2 + t];
    }
    ((float2*)&smI[0][2])[t] = viC;
    ((float2*)&smP[0][2])[t] = vpC;
    ((float2*)&smA[0][2])[t] = z2;
    ((float2*)&smB[0][2])[t] = z2;
    __syncthreads();

    int rn   = y0;            // row prefetched this body
    int ra   = y0 - 3;        // a/b row produced this body
    int ro   = y0 - 5;        // output row produced this body
    int oidx = y0 * W2 + t;   // output / output-I index (advances in main bodies)

#define BODY(P, DO_OUT)                                                          \
    {                                                                            \
        /* neighbor pair reads (aligned LDS.64, guards make edges zero) */       \
        const float2 vLI = *(const float2*)&smI[P][x0];                          \
        const float2 vRI = *(const float2*)&smI[P][x0 + 4];                      \
        const float2 vLP = *(const float2*)&smP[P][x0];                          \
        const float2 vRP = *(const float2*)&smP[P][x0 + 4];                      \
        const float2 vLA = *(const float2*)&smA[P][x0];                          \
        const float2 vRA = *(const float2*)&smA[P][x0 + 4];                      \
        const float2 vLB = *(const float2*)&smB[P][x0];                          \
        const float2 vRB = *(const float2*)&smB[P][x0 + 4];                      \
        /* prefetch input row rn (consumed 2 bodies later) */                    \
        float2 viF = z2, vpF = z2;                                               \
        if (rn < Hd) { viF = GI[rn * W2 + t]; vpF = GP[rn * W2 + t]; }           \
        rn++;                                                                    \
        /* shifted pairs for row viC/vpC */                                      \
        const float2 sLI = mk2(vLI.y, viC.x), sRI = mk2(viC.y, vRI.x);           \
        const float2 sLP = mk2(vLP.y, vpC.x), sRP = mk2(vpC.y, vRP.x);           \
        /* horizontal 3-sums (packed) */                                         \
        const float2 hI  = f2add(f2add(sLI, viC), sRI);                          \
        const float2 hP  = f2add(f2add(sLP, vpC), sRP);                          \
        const float2 hII = f2fma(sLI, sLI, f2fma(viC, viC, f2mul(sRI, sRI)));    \
        const float2 hIP = f2fma(sLI, sLP, f2fma(viC, vpC, f2mul(sRI, sRP)));    \
        /* vertical 3-row slide (packed) */                                      \
        const float2 SI  = f2add(psI,  hI);  psI  = f2add(lI,  hI);  lI  = hI;   \
        const float2 SP  = f2add(psP,  hP);  psP  = f2add(lP,  hP);  lP  = hP;   \
        const float2 SII = f2add(psII, hII); psII = f2add(lII, hII); lII = hII;  \
        const float2 SIP = f2add(psIP, hIP); psIP = f2add(lIP, hIP); lIP = hIP;  \
        /* a,b for row ra; rows outside [0,Hd) MUST be zero (ra=Hd sums rows    \
           Hd-1..Hd+1 which are NOT all zero) */                                 \
        const float invcyA = (ra == 0 || ra == Hd - 1) ? 0.5f : THIRD;           \
        const bool raOK = ((unsigned)ra < (unsigned)Hd);                         \
        ra++;                                                                    \
        float2 av = z2, bv = z2;                                                 \
        if (raOK) {                                                              \
            {                                                                    \
                const float inv = icx0 * invcyA;                                 \
                const float mI = SI.x * inv, mP = SP.x * inv;                    \
                const float var = fmaf(SII.x, inv, -mI * mI);                    \
                const float cov = fmaf(SIP.x, inv, -mI * mP);                    \
                const float a = __fdividef(cov, var + EPS);                      \
                av.x = a; bv.x = fmaf(-a, mI, mP);                               \
            }                                                                    \
            {                                                                    \
                const float inv = icx1 * invcyA;                                 \
                const float mI = SI.y * inv, mP = SP.y * inv;                    \
                const float var = fmaf(SII.y, inv, -mI * mI);                    \
                const float cov = fmaf(SIP.y, inv, -mI * mP);                    \
                const float a = __fdividef(cov, var + EPS);                      \
                av.y = a; bv.y = fmaf(-a, mI, mP);                               \
            }                                                                    \
        }                                                                        \
        /* a/b h-sums for row staged last body (avP) + vertical slide */         \
        const float2 sLA = mk2(vLA.y, avP.x), sRA = mk2(avP.y, vRA.x);           \
        const float2 sLB = mk2(vLB.y, bvP.x), sRB = mk2(bvP.y, vRB.x);           \
        const float2 hA = f2add(f2add(sLA, avP), sRA);                           \
        const float2 hB = f2add(f2add(sLB, bvP), sRB);                           \
        const float2 SA = f2add(psA, hA); psA = f2add(lA, hA); lA = hA;          \
        const float2 SB = f2add(psB, hB); psB = f2add(lB, hB); lB = hB;          \
        /* output row ro */                                                      \
        if (DO_OUT) {                                                            \
            const float invcyO = (ro == 0 || ro == Hd - 1) ? 0.5f : THIRD;       \
            const float2 vO = __ldg(&GI[oidx]);                                  \
            const float2 sc = mk2(icx0 * invcyO, icx1 * invcyO);                 \
            GO[oidx] = f2mul(f2fma(SA, vO, SB), sc);                             \
            oidx += W2;                                                          \
        }                                                                        \
        ro++;                                                                    \
        /* stage next buffer */                                                  \
        ((float2*)&smI[P ^ 1][2])[t] = viN;                                      \
        ((float2*)&smP[P ^ 1][2])[t] = vpN;                                      \
        ((float2*)&smA[P ^ 1][2])[t] = av;                                       \
        ((float2*)&smB[P ^ 1][2])[t] = bv;                                       \
        avP = av; bvP = bv;                                                      \
        viC = viN; vpC = vpN; viN = viF; vpN = vpF;                              \
        __syncthreads();                                                         \
    }

    // prologue: i = 0..4 (no outputs), parities 0,1,0,1,0
    BODY(0, false) BODY(1, false) BODY(0, false) BODY(1, false) BODY(0, false)

    // main: i = 5..68 (64 outputs), parities 1,0 repeated
    for (int k = 0; k < 32; ++k) {
        BODY(1, true)
        BODY(0, true)
    }
#undef BODY
}

extern "C" void kernel_launch(void* const* d_in, const int* in_sizes, int n_in,
                              void* d_out, int out_size) {
    const float* I = (const float*)d_in[0];   // input
    const float* P = (const float*)d_in[1];   // guide
    float* O = (float*)d_out;

    const int Z = in_sizes[0] / (Wd * Hd);    // B*C = 128
    dim3 block(NT, 1, 1);
    dim3 grid(Hd / RSTRIP, Z, 1);             // 8 x 128
    gf_kernel<<<grid, block>>>(I, P, O);
}

// round 10
// speedup vs baseline: 1.0048x; 1.0048x over previous
#include <cuda_runtime.h>

#define Wd 512
#define Hd 512
#define W2 (Wd / 2)
#define NT 256
#define RSTRIP 64
#define LDW 520            // padded row: [0,1] left guard, data [2..513], [514..] right guard
#define THIRD 0.3333333333333333f
#define EPS 0.01f

typedef unsigned long long ull;

static __device__ __forceinline__ ull U(float2 v) { ull r; memcpy(&r, &v, 8); return r; }
static __device__ __forceinline__ float2 F(ull u) { float2 v; memcpy(&v, &u, 8); return v; }

static __device__ __forceinline__ float2 f2add(float2 a, float2 b) {
    ull r; asm("add.rn.f32x2 %0,%1,%2;" : "=l"(r) : "l"(U(a)), "l"(U(b))); return F(r);
}
static __device__ __forceinline__ float2 f2mul(float2 a, float2 b) {
    ull r; asm("mul.rn.f32x2 %0,%1,%2;" : "=l"(r) : "l"(U(a)), "l"(U(b))); return F(r);
}
static __device__ __forceinline__ float2 f2fma(float2 a, float2 b, float2 c) {
    ull r; asm("fma.rn.f32x2 %0,%1,%2,%3;" : "=l"(r) : "l"(U(a)), "l"(U(b)), "l"(U(c))); return F(r);
}
static __device__ __forceinline__ float2 mk2(float a, float b) { float2 v; v.x = a; v.y = b; return v; }

__global__ __launch_bounds__(NT, 4)
void gf_kernel(const float* __restrict__ gI, const float* __restrict__ gP,
               float* __restrict__ gO)
{
    __shared__ __align__(16) float smI[2][LDW], smP[2][LDW], smA[2][LDW], smB[2][LDW];

    const int t  = threadIdx.x;
    const int x0 = 2 * t;                 // padded data index of own pair = x0+2
    const int y0 = blockIdx.x * RSTRIP;
    const size_t base = (size_t)blockIdx.y * (size_t)(Wd * Hd);
    const float2* __restrict__ GI = (const float2*)(gI + base);
    const float2* __restrict__ GP = (const float2*)(gP + base);
    float2* __restrict__ GO = (float2*)(gO + base);

    const float icx0 = (t == 0)      ? 0.5f : THIRD;   // count_include_pad=False col counts
    const float icx1 = (t == NT - 1) ? 0.5f : THIRD;

    // permanent zero guards (stores each iter touch only [2..513])
    if (t < 2) {
        const int g = (t == 0) ? 1 : 514;
        #pragma unroll
        for (int b = 0; b < 2; ++b) {
            smI[b][g] = 0.f; smP[b][g] = 0.f; smA[b][g] = 0.f; smB[b][g] = 0.f;
        }
    }

    const float2 z2 = mk2(0.f, 0.f);

    // vertical sliding state (pair-sum ps + last h-row l), all packed float2
    float2 psI = z2, lI = z2, psP = z2, lP = z2;
    float2 psII = z2, lII = z2, psIP = z2, lIP = z2;
    float2 psA = z2, lA = z2, psB = z2, lB = z2;
    float2 avP = z2, bvP = z2;

    // prologue rows y0-2 (cur) and y0-1 (next)
    float2 viC = z2, vpC = z2, viN = z2, vpN = z2;
    if (y0 >= 2) {
        viC = GI[(y0 - 2) * W2 + t]; vpC = GP[(y0 - 2) * W2 + t];
        viN = GI[(y0 - 1) * W2 + t]; vpN = GP[(y0 - 1) * W2 + t];
    }
    ((float2*)&smI[0][2])[t] = viC;
    ((float2*)&smP[0][2])[t] = vpC;
    ((float2*)&smA[0][2])[t] = z2;
    ((float2*)&smB[0][2])[t] = z2;
    __syncthreads();

    int rn   = y0;            // row prefetched this body
    int ra   = y0 - 3;        // a/b row produced this body
    int ro   = y0 - 5;        // output row produced this body
    int oidx = y0 * W2 + t;   // output / output-I index (advances in main bodies)

#define BODY(P, DO_OUT)                                                          \
    {                                                                            \
        /* neighbor pair reads (aligned LDS.64, guards make edges zero) */       \
        const float2 vLI = *(const float2*)&smI[P][x0];                          \
        const float2 vRI = *(const float2*)&smI[P][x0 + 4];                      \
        const float2 vLP = *(const float2*)&smP[P][x0];                          \
        const float2 vRP = *(const float2*)&smP[P][x0 + 4];                      \
        const float2 vLA = *(const float2*)&smA[P][x0];                          \
        const float2 vRA = *(const float2*)&smA[P][x0 + 4];                      \
        const float2 vLB = *(const float2*)&smB[P][x0];                          \
        const float2 vRB = *(const float2*)&smB[P][x0 + 4];                      \
        /* prefetch input row rn (consumed 2 bodies later) */                    \
        float2 viF = z2, vpF = z2;                                               \
        if (rn < Hd) { viF = GI[rn * W2 + t]; vpF = GP[rn * W2 + t]; }           \
        rn++;                                                                    \
        /* shifted pairs for row viC/vpC */                                      \
        const float2 sLI = mk2(vLI.y, viC.x), sRI = mk2(viC.y, vRI.x);           \
        const float2 sLP = mk2(vLP.y, vpC.x), sRP = mk2(vpC.y, vRP.x);           \
        /* horizontal 3-sums (packed) */                                         \
        const float2 hI  = f2add(f2add(sLI, viC), sRI);                          \
        const float2 hP  = f2add(f2add(sLP, vpC), sRP);                          \
        const float2 hII = f2fma(sLI, sLI, f2fma(viC, viC, f2mul(sRI, sRI)));    \
        const float2 hIP = f2fma(sLI, sLP, f2fma(viC, vpC, f2mul(sRI, sRP)));    \
        /* vertical 3-row slide (packed) */                                      \
        const float2 SI  = f2add(psI,  hI);  psI  = f2add(lI,  hI);  lI  = hI;   \
        const float2 SP  = f2add(psP,  hP);  psP  = f2add(lP,  hP);  lP  = hP;   \
        const float2 SII = f2add(psII, hII); psII = f2add(lII, hII); lII = hII;  \
        const float2 SIP = f2add(psIP, hIP); psIP = f2add(lIP, hIP); lIP = hIP;  \
        /* a,b for row ra; rows outside [0,Hd) MUST be zero (ra=Hd sums rows    \
           Hd-1..Hd+1 which are NOT all zero) */                                 \
        const float invcyA = (ra == 0 || ra == Hd - 1) ? 0.5f : THIRD;           \
        const bool raOK = ((unsigned)ra < (unsigned)Hd);                         \
        ra++;                                                                    \
        float2 av = z2, bv = z2;                                                 \
        if (raOK) {                                                              \
            {                                                                    \
                const float inv = icx0 * invcyA;                                 \
                const float mI = SI.x * inv, mP = SP.x * inv;                    \
                const float var = fmaf(SII.x, inv, -mI * mI);                    \
                const float cov = fmaf(SIP.x, inv, -mI * mP);                    \
                const float a = __fdividef(cov, var + EPS);                      \
                av.x = a; bv.x = fmaf(-a, mI, mP);                               \
            }                                                                    \
            {                                                                    \
                const float inv = icx1 * invcyA;                                 \
                const float mI = SI.y * inv, mP = SP.y * inv;                    \
                const float var = fmaf(SII.y, inv, -mI * mI);                    \
                const float cov = fmaf(SIP.y, inv, -mI * mP);                    \
                const float a = __fdividef(cov, var + EPS);                      \
                av.y = a; bv.y = fmaf(-a, mI, mP);                               \
            }                                                                    \
        }                                                                        \
        /* a/b h-sums for row staged last body (avP) + vertical slide */         \
        const float2 sLA = mk2(vLA.y, avP.x), sRA = mk2(avP.y, vRA.x);           \
        const float2 sLB = mk2(vLB.y, bvP.x), sRB = mk2(bvP.y, vRB.x);           \
        const float2 hA = f2add(f2add(sLA, avP), sRA);                           \
        const float2 hB = f2add(f2add(sLB, bvP), sRB);                           \
        const float2 SA = f2add(psA, hA); psA = f2add(lA, hA); lA = hA;          \
        const float2 SB = f2add(psB, hB); psB = f2add(lB, hB); lB = hB;          \
        /* output row ro */                                                      \
        if (DO_OUT) {                                                            \
            const float invcyO = (ro == 0 || ro == Hd - 1) ? 0.5f : THIRD;       \
            const float2 vO = __ldg(&GI[oidx]);                                  \
            const float2 sc = mk2(icx0 * invcyO, icx1 * invcyO);                 \
            GO[oidx] = f2mul(f2fma(SA, vO, SB), sc);                             \
            oidx += W2;                                                          \
        }                                                                        \
        ro++;                                                                    \
        /* stage next buffer */                                                  \
        ((float2*)&smI[P ^ 1][2])[t] = viN;                                      \
        ((float2*)&smP[P ^ 1][2])[t] = vpN;                                      \
        ((float2*)&smA[P ^ 1][2])[t] = av;                                       \
        ((float2*)&smB[P ^ 1][2])[t] = bv;                                       \
        avP = av; bvP = bv;                                                      \
        viC = viN; vpC = vpN; viN = viF; vpN = vpF;                              \
        __syncthreads();                                                         \
    }

    // prologue: i = 0..4 (no outputs), parities 0,1,0,1,0
    BODY(0, false) BODY(1, false) BODY(0, false) BODY(1, false) BODY(0, false)

    // main: i = 5..68 (64 outputs), parities 1,0 repeated
    for (int k = 0; k < 32; ++k) {
        BODY(1, true)
        BODY(0, true)
    }
#undef BODY
}

extern "C" void kernel_launch(void* const* d_in, const int* in_sizes, int n_in,
                              void* d_out, int out_size) {
    const float* I = (const float*)d_in[0];   // input
    const float* P = (const float*)d_in[1];   // guide
    float* O = (float*)d_out;

    const int Z = in_sizes[0] / (Wd * Hd);    // B*C = 128
    dim3 block(NT, 1, 1);
    dim3 grid(Hd / RSTRIP, Z, 1);             // 8 x 128
    gf_kernel<<<grid, block>>>(I, P, O);
}